// round 1
// baseline (speedup 1.0000x reference)
#include <cuda_runtime.h>
#include <cuda_bf16.h>
#include <math.h>

#define NPIX  65536
#define WIMG  256
#define EPSN  1e-12f

// ---------------- scratch (device globals; no allocation allowed) -----------
// y = 1x1-conv output, [branch*4+batch][192][N] fp32
__device__ float g_y[8ull * 192 * 65536];          // 384 MB
__device__ float g_G[8 * 8 * 8 * 8];               // [bz][head][c][d] gram
__device__ float g_nq[8 * 64];                     // [bz][head*8+c] sum q^2
__device__ float g_nk[8 * 64];
__device__ float g_M[8 * 64 * 64];                 // [bz][o][j] folded matrices

// ---------------- K0: zero the global accumulators --------------------------
__global__ __launch_bounds__(256) void k0_zero() {
    int t = blockIdx.x * 256 + threadIdx.x;
    if (t < 4096) g_G[t] = 0.f;
    if (t < 512) { g_nq[t] = 0.f; g_nk[t] = 0.f; }
}

// ---------------- K1: y = W_qkv @ x (per branch/batch), 192x64xN GEMM -------
// grid (N/128, 3, 8) ; block 256 ; dyn smem = (64*128 + 64*64)*4 = 49152 B
__global__ __launch_bounds__(256) void k1_qkv(const float* __restrict__ x,
                                              const float* __restrict__ w1,
                                              const float* __restrict__ w2) {
    extern __shared__ float sm[];
    float* xs = sm;              // [ic][128]
    float* ws = sm + 64 * 128;   // [ic][64 oc]

    const int t   = threadIdx.x;
    const int bz  = blockIdx.z;            // br*4 + b
    const int br  = bz >> 2, b = bz & 3;
    const int oct = blockIdx.y;            // 0..2 -> oc base oct*64
    const int n0  = blockIdx.x * 128;

    const float* w  = (br ? w2 : w1) + oct * 64 * 64;
    const float* xb = x + (size_t)(b * 128 + br * 64) * NPIX;
    float*       y  = g_y + (size_t)(bz * 192 + oct * 64) * NPIX;

    // weights: w[oc][ic] -> ws[ic][oc] (smem writes conflict-free; global
    // strided reads hit L2 after first block)
    for (int i = t; i < 64 * 64; i += 256) {
        int ic = i >> 6, oc = i & 63;
        ws[ic * 64 + oc] = w[oc * 64 + ic];
    }
    // x tile [64][128] vectorized
    for (int i = t; i < 64 * 32; i += 256) {
        int ic = i >> 5, f4 = i & 31;
        *(float4*)&xs[ic * 128 + f4 * 4] =
            *(const float4*)&xb[(size_t)ic * NPIX + n0 + f4 * 4];
    }
    __syncthreads();

    const int px0 = (t & 31) * 4;      // 4 consecutive pixels
    const int o0  = (t >> 5) * 8;      // 8 output channels
    float acc[8][4];
#pragma unroll
    for (int i = 0; i < 8; i++)
#pragma unroll
        for (int j = 0; j < 4; j++) acc[i][j] = 0.f;

#pragma unroll 16
    for (int ic = 0; ic < 64; ++ic) {
        float4 xv = *(float4*)&xs[ic * 128 + px0];
        float4 wa = *(float4*)&ws[ic * 64 + o0];
        float4 wb = *(float4*)&ws[ic * 64 + o0 + 4];
        float w8[8] = {wa.x, wa.y, wa.z, wa.w, wb.x, wb.y, wb.z, wb.w};
#pragma unroll
        for (int oo = 0; oo < 8; ++oo) {
            float wv = w8[oo];
            acc[oo][0] += wv * xv.x;
            acc[oo][1] += wv * xv.y;
            acc[oo][2] += wv * xv.z;
            acc[oo][3] += wv * xv.w;
        }
    }
#pragma unroll
    for (int oo = 0; oo < 8; ++oo) {
        float4 v = make_float4(acc[oo][0], acc[oo][1], acc[oo][2], acc[oo][3]);
        *(float4*)&y[(size_t)(o0 + oo) * NPIX + n0 + px0] = v;
    }
}

// ---------------- K2: depthwise 3x3 on q,k + gram / norm reductions ---------
// grid (256 tiles, 8 heads, 8 bz); block 256; static smem ~37 KB
__global__ __launch_bounds__(256) void k2_dw_gram(const float* __restrict__ wdw1,
                                                  const float* __restrict__ wdw2) {
    __shared__ float ys[16 * 324];     // 16 ch x 18x18 halo
    __shared__ float qs[8 * 256];
    __shared__ float ks[8 * 256];
    __shared__ float wdws[16 * 9];

    const int t    = threadIdx.x;
    const int tile = blockIdx.x;
    const int h    = blockIdx.y;
    const int bz   = blockIdx.z;
    const int br   = bz >> 2;
    const int ty = tile >> 4, tx = tile & 15;
    const int r0 = ty * 16, c0 = tx * 16;

    const float* ybase = g_y + (size_t)bz * 192 * NPIX;
    const float* wdw   = br ? wdw2 : wdw1;

    if (t < 144) {
        int ch = t / 9, kk = t - ch * 9;
        int cg = (ch < 8) ? (h * 8 + ch) : (64 + h * 8 + (ch - 8));
        wdws[ch * 9 + kk] = wdw[cg * 9 + kk];
    }
#pragma unroll
    for (int ch = 0; ch < 16; ++ch) {
        int cg = (ch < 8) ? (h * 8 + ch) : (64 + h * 8 + (ch - 8));
        const float* yc = ybase + (size_t)cg * NPIX;
        for (int hp = t; hp < 324; hp += 256) {
            int row = hp / 18;
            int hy = r0 + row - 1;
            int hx = c0 + (hp - row * 18) - 1;
            float v = 0.f;
            if ((unsigned)hy < 256u && (unsigned)hx < 256u)
                v = yc[hy * WIMG + hx];
            ys[ch * 324 + hp] = v;
        }
    }
    __syncthreads();

    {   // depthwise conv, one inner pixel per thread
        const int iy = t >> 4, ix = t & 15;
#pragma unroll
        for (int ch = 0; ch < 16; ++ch) {
            float s = 0.f;
#pragma unroll
            for (int ky = 0; ky < 3; ++ky)
#pragma unroll
                for (int kx = 0; kx < 3; ++kx)
                    s += ys[ch * 324 + (iy + ky) * 18 + ix + kx] *
                         wdws[ch * 9 + ky * 3 + kx];
            if (ch < 8) qs[ch * 256 + t] = s;
            else        ks[(ch - 8) * 256 + t] = s;
        }
    }
    __syncthreads();

    // 80 reduction entries (64 gram + 8 nq + 8 nk), 10 per warp
    const int wid = t >> 5, lane = t & 31;
    for (int e = wid; e < 80; e += 8) {
        float s = 0.f;
        if (e < 64) {
            int c = e >> 3, d = e & 7;
#pragma unroll
            for (int j = 0; j < 8; ++j)
                s += qs[c * 256 + lane + 32 * j] * ks[d * 256 + lane + 32 * j];
        } else if (e < 72) {
            int c = e - 64;
#pragma unroll
            for (int j = 0; j < 8; ++j) {
                float v = qs[c * 256 + lane + 32 * j];
                s += v * v;
            }
        } else {
            int c = e - 72;
#pragma unroll
            for (int j = 0; j < 8; ++j) {
                float v = ks[c * 256 + lane + 32 * j];
                s += v * v;
            }
        }
#pragma unroll
        for (int off = 16; off; off >>= 1)
            s += __shfl_xor_sync(0xffffffffu, s, off);
        if (lane == 0) {
            if (e < 64)       atomicAdd(&g_G[bz * 512 + h * 64 + (e >> 3) * 8 + (e & 7)], s);
            else if (e < 72)  atomicAdd(&g_nq[bz * 64 + h * 8 + (e - 64)], s);
            else              atomicAdd(&g_nk[bz * 64 + h * 8 + (e - 72)], s);
        }
    }
}

// ---------------- K3: attn = softmax(G/(|q||k|) * t); M = w_po @ attn -------
// grid 8 blocks; block 256
__global__ __launch_bounds__(256) void k3_attn(const float* __restrict__ wpo1,
                                               const float* __restrict__ wpo2,
                                               const float* __restrict__ t1,
                                               const float* __restrict__ t2) {
    __shared__ float attn[64 * 8];     // [h*8+c][d]
    __shared__ float qn[64], kn[64];
    const int bz = blockIdx.x;
    const int br = bz >> 2;
    const int t  = threadIdx.x;

    if (t < 64) {
        qn[t] = fmaxf(sqrtf(g_nq[bz * 64 + t]), EPSN);
        kn[t] = fmaxf(sqrtf(g_nk[bz * 64 + t]), EPSN);
    }
    __syncthreads();
    if (t < 64) {
        int h = t >> 3;
        float tv = (br ? t2 : t1)[h];
        float L[8], mx = -1e30f;
#pragma unroll
        for (int d = 0; d < 8; ++d) {
            L[d] = g_G[bz * 512 + t * 8 + d] / (qn[t] * kn[h * 8 + d]) * tv;
            mx = fmaxf(mx, L[d]);
        }
        float ssum = 0.f;
#pragma unroll
        for (int d = 0; d < 8; ++d) { L[d] = expf(L[d] - mx); ssum += L[d]; }
        float inv = 1.f / ssum;
#pragma unroll
        for (int d = 0; d < 8; ++d) attn[t * 8 + d] = L[d] * inv;
    }
    __syncthreads();
    const float* wpo = br ? wpo2 : wpo1;
    for (int i = t; i < 4096; i += 256) {
        int o = i >> 6, col = i & 63;
        int h = col >> 3, d = col & 7;
        float m = 0.f;
#pragma unroll
        for (int c = 0; c < 8; ++c)
            m += wpo[o * 64 + h * 8 + c] * attn[(h * 8 + c) * 8 + d];
        g_M[bz * 4096 + i] = m;   // [o][col=j]
    }
}

// ---------------- K4: out = M @ dw3x3(y_v_otherbranch) ----------------------
// grid (256 tiles, 8 = brout*4+b); block 256;
// dyn smem = (64*324 + 64*256 + 64*64)*4 = 164864 B
__global__ __launch_bounds__(256) void k4_out(const float* __restrict__ wdw1,
                                              const float* __restrict__ wdw2,
                                              float* __restrict__ out) {
    extern __shared__ float sm[];
    float* ys = sm;                  // [64][324]
    float* vs = ys + 64 * 324;       // [64][256]
    float* Ms = vs + 64 * 256;       // [j][o] transposed
    __shared__ float wdws[64 * 9];

    const int t     = threadIdx.x;
    const int bz    = blockIdx.y;
    const int brout = bz >> 2, b = bz & 3;
    const int vbr   = 1 - brout;               // cross-branch V swap
    const int tile  = blockIdx.x;
    const int ty = tile >> 4, tx = tile & 15;
    const int r0 = ty * 16, c0 = tx * 16;

    const float* wdw = (vbr ? wdw2 : wdw1) + 128 * 9;                  // v part
    const float* yv  = g_y + (size_t)((vbr * 4 + b) * 192 + 128) * NPIX;
    const float* Mg  = g_M + (size_t)bz * 4096;

    for (int i = t; i < 4096; i += 256) {
        int j = i >> 6, o = i & 63;
        Ms[i] = Mg[o * 64 + j];
    }
    for (int i = t; i < 576; i += 256) wdws[i] = wdw[i];

#pragma unroll 2
    for (int ch = 0; ch < 64; ++ch) {
        const float* yc = yv + (size_t)ch * NPIX;
        for (int hp = t; hp < 324; hp += 256) {
            int row = hp / 18;
            int hy = r0 + row - 1;
            int hx = c0 + (hp - row * 18) - 1;
            float v = 0.f;
            if ((unsigned)hy < 256u && (unsigned)hx < 256u)
                v = yc[hy * WIMG + hx];
            ys[ch * 324 + hp] = v;
        }
    }
    __syncthreads();
    {   // depthwise conv of v channels
        const int iy = t >> 4, ix = t & 15;
#pragma unroll 4
        for (int ch = 0; ch < 64; ++ch) {
            float s = 0.f;
#pragma unroll
            for (int ky = 0; ky < 3; ++ky)
#pragma unroll
                for (int kx = 0; kx < 3; ++kx)
                    s += ys[ch * 324 + (iy + ky) * 18 + ix + kx] *
                         wdws[ch * 9 + ky * 3 + kx];
            vs[ch * 256 + t] = s;
        }
    }
    __syncthreads();

    // GEMM: out[o0..o0+15][4 pixels] ; 64 accumulators per thread
    const int pix = t & 63, og = t >> 6, o0 = og * 16;
    float acc[16][4];
#pragma unroll
    for (int i = 0; i < 16; i++)
#pragma unroll
        for (int j = 0; j < 4; j++) acc[i][j] = 0.f;

#pragma unroll 8
    for (int j = 0; j < 64; ++j) {
        float4 v4 = *(float4*)&vs[j * 256 + pix * 4];
#pragma unroll
        for (int oq = 0; oq < 4; ++oq) {
            float4 m = *(float4*)&Ms[j * 64 + o0 + oq * 4];
            float mm[4] = {m.x, m.y, m.z, m.w};
#pragma unroll
            for (int r = 0; r < 4; ++r) {
                acc[oq * 4 + r][0] += mm[r] * v4.x;
                acc[oq * 4 + r][1] += mm[r] * v4.y;
                acc[oq * 4 + r][2] += mm[r] * v4.z;
                acc[oq * 4 + r][3] += mm[r] * v4.w;
            }
        }
    }
    const int p0 = pix * 4;
    const int py = p0 >> 4, px = p0 & 15;
    const size_t nb = (size_t)(r0 + py) * WIMG + c0 + px;
#pragma unroll
    for (int oo = 0; oo < 16; ++oo) {
        float4 v = make_float4(acc[oo][0], acc[oo][1], acc[oo][2], acc[oo][3]);
        *(float4*)&out[(size_t)(b * 128 + brout * 64 + o0 + oo) * NPIX + nb] = v;
    }
}

// ---------------- launch ----------------------------------------------------
extern "C" void kernel_launch(void* const* d_in, const int* in_sizes, int n_in,
                              void* d_out, int out_size) {
    const float* x      = (const float*)d_in[0];
    const float* w_qkv1 = (const float*)d_in[1];
    const float* w_qkv2 = (const float*)d_in[2];
    const float* w_dw1  = (const float*)d_in[3];
    const float* w_dw2  = (const float*)d_in[4];
    const float* w_po1  = (const float*)d_in[5];
    const float* w_po2  = (const float*)d_in[6];
    const float* t1     = (const float*)d_in[7];
    const float* t2     = (const float*)d_in[8];
    float* out = (float*)d_out;

    const int K1_SMEM = (64 * 128 + 64 * 64) * 4;                   // 49152
    const int K4_SMEM = (64 * 324 + 64 * 256 + 64 * 64) * 4;        // 164864
    cudaFuncSetAttribute(k1_qkv, cudaFuncAttributeMaxDynamicSharedMemorySize, K1_SMEM);
    cudaFuncSetAttribute(k4_out, cudaFuncAttributeMaxDynamicSharedMemorySize, K4_SMEM);

    k0_zero<<<16, 256>>>();
    k1_qkv<<<dim3(NPIX / 128, 3, 8), 256, K1_SMEM>>>(x, w_qkv1, w_qkv2);
    k2_dw_gram<<<dim3(256, 8, 8), 256>>>(w_dw1, w_dw2);
    k3_attn<<<8, 256>>>(w_po1, w_po2, t1, t2);
    k4_out<<<dim3(256, 8), 256, K4_SMEM>>>(w_dw1, w_dw2, out);
}

// round 4
// speedup vs baseline: 1.0800x; 1.0800x over previous
#include <cuda_runtime.h>
#include <cuda_bf16.h>
#include <cstdint>
#include <math.h>

#define NPIX  65536
#define WIMG  256
#define EPSN  1e-12f

// ---------------- scratch (device globals; no allocation allowed) -----------
__device__ float g_y[8ull * 192 * 65536];          // 384 MB qkv activations
__device__ float g_G[8 * 8 * 8 * 8];               // [bz][head][c][d] gram
__device__ float g_nq[8 * 64];
__device__ float g_nk[8 * 64];
__device__ float g_M[8 * 64 * 64];                 // folded w_po @ attn

// ---------------- warp-level TF32 MMA (sm_80+ PTX, works on compute_100) ----
__device__ __forceinline__ uint32_t f2tf32(float f) {
    uint32_t u;
    asm("cvt.rna.tf32.f32 %0, %1;" : "=r"(u) : "f"(f));
    return u;
}
__device__ __forceinline__ void mma_tf32(float c[4],
                                         uint32_t a0, uint32_t a1,
                                         uint32_t a2, uint32_t a3,
                                         uint32_t b0, uint32_t b1) {
    asm volatile(
        "mma.sync.aligned.m16n8k8.row.col.f32.tf32.tf32.f32 "
        "{%0,%1,%2,%3}, {%4,%5,%6,%7}, {%8,%9}, {%0,%1,%2,%3};"
        : "+f"(c[0]), "+f"(c[1]), "+f"(c[2]), "+f"(c[3])
        : "r"(a0), "r"(a1), "r"(a2), "r"(a3), "r"(b0), "r"(b1));
}

// ---------------- K0: zero the global accumulators --------------------------
__global__ __launch_bounds__(256) void k0_zero() {
    int t = blockIdx.x * 256 + threadIdx.x;
    if (t < 4096) g_G[t] = 0.f;
    if (t < 512) { g_nq[t] = 0.f; g_nk[t] = 0.f; }
}

// ---------------- K1: y = W_qkv @ x via tensor-core TF32 mma ---------------
// grid (512, 8); block 256 (8 warps).
// Per block: D[128 px][192 oc] = x^T[128 px][64 ic] @ W^T[64 ic][192 oc].
// Warp w owns oc range [w*24, w*24+24) (3 n-chunks of 8); m = 8 chunks of 16 px;
// k = 8 chunks of 8 ic. B (weights) preloaded in 48 regs; A from padded smem.
#define XS_STRIDE 65
__global__ __launch_bounds__(256) void k1_qkv_mma(const float* __restrict__ x,
                                                  const float* __restrict__ w1,
                                                  const float* __restrict__ w2) {
    __shared__ uint32_t xs[128 * XS_STRIDE];   // 33.3 KB, tf32-rounded bits
    const int t = threadIdx.x, wid = t >> 5, lane = t & 31;
    const int gid = lane >> 2, tig = lane & 3;
    const int bz = blockIdx.y, br = bz >> 2, b = bz & 3;
    const float* W  = br ? w2 : w1;                              // [192][64]
    const float* xb = x + (size_t)(b * 128 + br * 64) * NPIX;    // [64][N]
    float*       yb = g_y + (size_t)bz * 192 * NPIX;             // [192][N]
    const int n0 = blockIdx.x * 128;
    const int ocbase = wid * 24;

    // Preload B fragments: b0 = W[oc = n][ic = k] with n=gid, k=tig (col-major B).
    uint32_t bf[3][8][2];
#pragma unroll
    for (int j = 0; j < 3; ++j) {
        const int oc = ocbase + j * 8 + gid;
#pragma unroll
        for (int k = 0; k < 8; ++k) {
            bf[j][k][0] = f2tf32(W[oc * 64 + k * 8 + tig]);
            bf[j][k][1] = f2tf32(W[oc * 64 + k * 8 + tig + 4]);
        }
    }

    // Load + transpose x tile: global [ic][px] coalesced -> smem [px][ic].
    for (int i = t; i < 64 * 32; i += 256) {
        const int ic = i >> 5, f = i & 31;
        float4 v = *(const float4*)(xb + (size_t)ic * NPIX + n0 + f * 4);
        const int px = f * 4;
        xs[(px + 0) * XS_STRIDE + ic] = f2tf32(v.x);
        xs[(px + 1) * XS_STRIDE + ic] = f2tf32(v.y);
        xs[(px + 2) * XS_STRIDE + ic] = f2tf32(v.z);
        xs[(px + 3) * XS_STRIDE + ic] = f2tf32(v.w);
    }
    __syncthreads();

#pragma unroll
    for (int m = 0; m < 8; ++m) {
        float acc[3][4] = {};
        const int r0 = m * 16 + gid;
#pragma unroll
        for (int k = 0; k < 8; ++k) {
            const uint32_t a0 = xs[r0 * XS_STRIDE + k * 8 + tig];
            const uint32_t a1 = xs[(r0 + 8) * XS_STRIDE + k * 8 + tig];
            const uint32_t a2 = xs[r0 * XS_STRIDE + k * 8 + tig + 4];
            const uint32_t a3 = xs[(r0 + 8) * XS_STRIDE + k * 8 + tig + 4];
#pragma unroll
            for (int j = 0; j < 3; ++j)
                mma_tf32(acc[j], a0, a1, a2, a3, bf[j][k][0], bf[j][k][1]);
        }
#pragma unroll
        for (int j = 0; j < 3; ++j) {
            const int col = ocbase + j * 8 + tig * 2;
            yb[(size_t)col * NPIX + n0 + r0]           = acc[j][0];
            yb[(size_t)(col + 1) * NPIX + n0 + r0]     = acc[j][1];
            yb[(size_t)col * NPIX + n0 + r0 + 8]       = acc[j][2];
            yb[(size_t)(col + 1) * NPIX + n0 + r0 + 8] = acc[j][3];
        }
    }
}

// ---------------- K2: depthwise 3x3 on q,k + gram / norm reductions ---------
__global__ __launch_bounds__(256) void k2_dw_gram(const float* __restrict__ wdw1,
                                                  const float* __restrict__ wdw2) {
    __shared__ float ys[16 * 324];
    __shared__ float qs[8 * 256];
    __shared__ float ks[8 * 256];
    __shared__ float wdws[16 * 9];

    const int t    = threadIdx.x;
    const int tile = blockIdx.x;
    const int h    = blockIdx.y;
    const int bz   = blockIdx.z;
    const int br   = bz >> 2;
    const int ty = tile >> 4, tx = tile & 15;
    const int r0 = ty * 16, c0 = tx * 16;

    const float* ybase = g_y + (size_t)bz * 192 * NPIX;
    const float* wdw   = br ? wdw2 : wdw1;

    if (t < 144) {
        int ch = t / 9, kk = t - ch * 9;
        int cg = (ch < 8) ? (h * 8 + ch) : (64 + h * 8 + (ch - 8));
        wdws[ch * 9 + kk] = wdw[cg * 9 + kk];
    }
#pragma unroll
    for (int ch = 0; ch < 16; ++ch) {
        int cg = (ch < 8) ? (h * 8 + ch) : (64 + h * 8 + (ch - 8));
        const float* yc = ybase + (size_t)cg * NPIX;
        for (int hp = t; hp < 324; hp += 256) {
            int row = hp / 18;
            int hy = r0 + row - 1;
            int hx = c0 + (hp - row * 18) - 1;
            float v = 0.f;
            if ((unsigned)hy < 256u && (unsigned)hx < 256u)
                v = yc[hy * WIMG + hx];
            ys[ch * 324 + hp] = v;
        }
    }
    __syncthreads();

    {
        const int iy = t >> 4, ix = t & 15;
#pragma unroll
        for (int ch = 0; ch < 16; ++ch) {
            float s = 0.f;
#pragma unroll
            for (int ky = 0; ky < 3; ++ky)
#pragma unroll
                for (int kx = 0; kx < 3; ++kx)
                    s += ys[ch * 324 + (iy + ky) * 18 + ix + kx] *
                         wdws[ch * 9 + ky * 3 + kx];
            if (ch < 8) qs[ch * 256 + t] = s;
            else        ks[(ch - 8) * 256 + t] = s;
        }
    }
    __syncthreads();

    const int wid = t >> 5, lane = t & 31;
    for (int e = wid; e < 80; e += 8) {
        float s = 0.f;
        if (e < 64) {
            int c = e >> 3, d = e & 7;
#pragma unroll
            for (int j = 0; j < 8; ++j)
                s += qs[c * 256 + lane + 32 * j] * ks[d * 256 + lane + 32 * j];
        } else if (e < 72) {
            int c = e - 64;
#pragma unroll
            for (int j = 0; j < 8; ++j) {
                float v = qs[c * 256 + lane + 32 * j];
                s += v * v;
            }
        } else {
            int c = e - 72;
#pragma unroll
            for (int j = 0; j < 8; ++j) {
                float v = ks[c * 256 + lane + 32 * j];
                s += v * v;
            }
        }
#pragma unroll
        for (int off = 16; off; off >>= 1)
            s += __shfl_xor_sync(0xffffffffu, s, off);
        if (lane == 0) {
            if (e < 64)       atomicAdd(&g_G[bz * 512 + h * 64 + (e >> 3) * 8 + (e & 7)], s);
            else if (e < 72)  atomicAdd(&g_nq[bz * 64 + h * 8 + (e - 64)], s);
            else              atomicAdd(&g_nk[bz * 64 + h * 8 + (e - 72)], s);
        }
    }
}

// ---------------- K3: attn softmax + fold M = w_po @ attn -------------------
__global__ __launch_bounds__(256) void k3_attn(const float* __restrict__ wpo1,
                                               const float* __restrict__ wpo2,
                                               const float* __restrict__ t1,
                                               const float* __restrict__ t2) {
    __shared__ float attn[64 * 8];
    __shared__ float qn[64], kn[64];
    const int bz = blockIdx.x;
    const int br = bz >> 2;
    const int t  = threadIdx.x;

    if (t < 64) {
        qn[t] = fmaxf(sqrtf(g_nq[bz * 64 + t]), EPSN);
        kn[t] = fmaxf(sqrtf(g_nk[bz * 64 + t]), EPSN);
    }
    __syncthreads();
    if (t < 64) {
        int h = t >> 3;
        float tv = (br ? t2 : t1)[h];
        float L[8], mx = -1e30f;
#pragma unroll
        for (int d = 0; d < 8; ++d) {
            L[d] = g_G[bz * 512 + t * 8 + d] / (qn[t] * kn[h * 8 + d]) * tv;
            mx = fmaxf(mx, L[d]);
        }
        float ssum = 0.f;
#pragma unroll
        for (int d = 0; d < 8; ++d) { L[d] = expf(L[d] - mx); ssum += L[d]; }
        float inv = 1.f / ssum;
#pragma unroll
        for (int d = 0; d < 8; ++d) attn[t * 8 + d] = L[d] * inv;
    }
    __syncthreads();
    const float* wpo = br ? wpo2 : wpo1;
    for (int i = t; i < 4096; i += 256) {
        int o = i >> 6, col = i & 63;
        int h = col >> 3, d = col & 7;
        float m = 0.f;
#pragma unroll
        for (int c = 0; c < 8; ++c)
            m += wpo[o * 64 + h * 8 + c] * attn[(h * 8 + c) * 8 + d];
        g_M[bz * 4096 + i] = m;
    }
}

// ---------------- K4: out = M @ dw3x3(y_v_otherbranch) ----------------------
__global__ __launch_bounds__(256) void k4_out(const float* __restrict__ wdw1,
                                              const float* __restrict__ wdw2,
                                              float* __restrict__ out) {
    extern __shared__ float sm[];
    float* ys = sm;                  // [64][324]
    float* vs = ys + 64 * 324;       // [64][256]
    float* Ms = vs + 64 * 256;       // [j][o] transposed
    __shared__ float wdws[64 * 9];

    const int t     = threadIdx.x;
    const int bz    = blockIdx.y;
    const int brout = bz >> 2, b = bz & 3;
    const int vbr   = 1 - brout;
    const int tile  = blockIdx.x;
    const int ty = tile >> 4, tx = tile & 15;
    const int r0 = ty * 16, c0 = tx * 16;

    const float* wdw = (vbr ? wdw2 : wdw1) + 128 * 9;
    const float* yv  = g_y + (size_t)((vbr * 4 + b) * 192 + 128) * NPIX;
    const float* Mg  = g_M + (size_t)bz * 4096;

    for (int i = t; i < 4096; i += 256) {
        int j = i >> 6, o = i & 63;
        Ms[i] = Mg[o * 64 + j];
    }
    for (int i = t; i < 576; i += 256) wdws[i] = wdw[i];

#pragma unroll 2
    for (int ch = 0; ch < 64; ++ch) {
        const float* yc = yv + (size_t)ch * NPIX;
        for (int hp = t; hp < 324; hp += 256) {
            int row = hp / 18;
            int hy = r0 + row - 1;
            int hx = c0 + (hp - row * 18) - 1;
            float v = 0.f;
            if ((unsigned)hy < 256u && (unsigned)hx < 256u)
                v = yc[hy * WIMG + hx];
            ys[ch * 324 + hp] = v;
        }
    }
    __syncthreads();
    {
        const int iy = t >> 4, ix = t & 15;
#pragma unroll 4
        for (int ch = 0; ch < 64; ++ch) {
            float s = 0.f;
#pragma unroll
            for (int ky = 0; ky < 3; ++ky)
#pragma unroll
                for (int kx = 0; kx < 3; ++kx)
                    s += ys[ch * 324 + (iy + ky) * 18 + ix + kx] *
                         wdws[ch * 9 + ky * 3 + kx];
            vs[ch * 256 + t] = s;
        }
    }
    __syncthreads();

    const int pix = t & 63, og = t >> 6, o0 = og * 16;
    float acc[16][4];
#pragma unroll
    for (int i = 0; i < 16; i++)
#pragma unroll
        for (int j = 0; j < 4; j++) acc[i][j] = 0.f;

#pragma unroll 8
    for (int j = 0; j < 64; ++j) {
        float4 v4 = *(float4*)&vs[j * 256 + pix * 4];
#pragma unroll
        for (int oq = 0; oq < 4; ++oq) {
            float4 m = *(float4*)&Ms[j * 64 + o0 + oq * 4];
            float mm[4] = {m.x, m.y, m.z, m.w};
#pragma unroll
            for (int r = 0; r < 4; ++r) {
                acc[oq * 4 + r][0] += mm[r] * v4.x;
                acc[oq * 4 + r][1] += mm[r] * v4.y;
                acc[oq * 4 + r][2] += mm[r] * v4.z;
                acc[oq * 4 + r][3] += mm[r] * v4.w;
            }
        }
    }
    const int p0 = pix * 4;
    const int py = p0 >> 4, px = p0 & 15;
    const size_t nb = (size_t)(r0 + py) * WIMG + c0 + px;
#pragma unroll
    for (int oo = 0; oo < 16; ++oo) {
        float4 v = make_float4(acc[oo][0], acc[oo][1], acc[oo][2], acc[oo][3]);
        *(float4*)&out[(size_t)(b * 128 + brout * 64 + o0 + oo) * NPIX + nb] = v;
    }
}

// ---------------- launch ----------------------------------------------------
extern "C" void kernel_launch(void* const* d_in, const int* in_sizes, int n_in,
                              void* d_out, int out_size) {
    const float* x      = (const float*)d_in[0];
    const float* w_qkv1 = (const float*)d_in[1];
    const float* w_qkv2 = (const float*)d_in[2];
    const float* w_dw1  = (const float*)d_in[3];
    const float* w_dw2  = (const float*)d_in[4];
    const float* w_po1  = (const float*)d_in[5];
    const float* w_po2  = (const float*)d_in[6];
    const float* t1     = (const float*)d_in[7];
    const float* t2     = (const float*)d_in[8];
    float* out = (float*)d_out;

    const int K4_SMEM = (64 * 324 + 64 * 256 + 64 * 64) * 4;        // 164864
    cudaFuncSetAttribute(k4_out, cudaFuncAttributeMaxDynamicSharedMemorySize, K4_SMEM);

    k0_zero<<<16, 256>>>();
    k1_qkv_mma<<<dim3(512, 8), 256>>>(x, w_qkv1, w_qkv2);
    k2_dw_gram<<<dim3(256, 8, 8), 256>>>(w_dw1, w_dw2);
    k3_attn<<<8, 256>>>(w_po1, w_po2, t1, t2);
    k4_out<<<dim3(256, 8), 256, K4_SMEM>>>(w_dw1, w_dw2, out);
}